// round 5
// baseline (speedup 1.0000x reference)
#include <cuda_runtime.h>
#include <cstdint>

#define B_    8
#define T_    4096
#define R_    1024
#define F_    64
#define I_    32
#define KTOT  96            // F_ + I_
#define NBLK  128           // scan blocks (8 rows of W_hh each)
#define NTHR  256
#define NGRP  8             // barrier counter/flag groups

// ---------------- device scratch (no allocations allowed) ----------------
__device__ float    g_h[2][R_][B_];                   // ping-pong hidden state [buf][k][b]
__device__ __align__(128) unsigned g_cnt[NGRP * 32];  // arrival counters, 1/128B line
__device__ __align__(128) unsigned g_flag[NGRP * 32]; // epoch flags, 1/128B line

// ---------------- helpers ----------------
__device__ __forceinline__ unsigned long long pack2(float a, float b) {
    unsigned long long r;
    asm("mov.b64 %0, {%1, %2};" : "=l"(r) : "f"(a), "f"(b));
    return r;
}
__device__ __forceinline__ void fma2(unsigned long long& d, unsigned long long a, unsigned long long b) {
    asm("fma.rn.f32x2 %0, %1, %2, %0;" : "+l"(d) : "l"(a), "l"(b));
}
__device__ __forceinline__ unsigned long long add2(unsigned long long a, unsigned long long b) {
    unsigned long long r;
    asm("add.rn.f32x2 %0, %1, %2;" : "=l"(r) : "l"(a), "l"(b));
    return r;
}
__device__ __forceinline__ float2 unpack2(unsigned long long v) {
    float2 f;
    asm("mov.b64 {%0, %1}, %2;" : "=f"(f.x), "=f"(f.y) : "l"(v));
    return f;
}
__device__ __forceinline__ float tanh_fast(float x) {
    float y;
    asm("tanh.approx.f32 %0, %1;" : "=f"(y) : "f"(x));
    return y;
}

template <int HALF>
__device__ __forceinline__ void reduce_round(unsigned long long* a, int lane, int d) {
    const bool hi = (lane & d) != 0;
#pragma unroll
    for (int i = 0; i < HALF; i++) {
        unsigned long long send = hi ? a[i] : a[i + HALF];
        unsigned long long keep = hi ? a[i + HALF] : a[i];
        unsigned long long recv = __shfl_xor_sync(0xffffffffu, send, d);
        a[i] = add2(keep, recv);
    }
}

// ---------------- drive GEMM (+ folded reset): out[bt][r] = X @ [Wfb|Win]^T + b ----
#define DRIVE_SMEM ((64 + 128) * 97 * 4)

__global__ __launch_bounds__(256) void drive_kernel(
    const float* __restrict__ fb, const float* __restrict__ drv,
    const float* __restrict__ Wfb, const float* __restrict__ Win,
    const float* __restrict__ bias, float* __restrict__ out)
{
    extern __shared__ float smem[];
    float (*xs)[97]  = (float (*)[97])smem;              // [64][97]
    float (*wsh)[97] = (float (*)[97])(smem + 64 * 97);  // [128][97]

    const int r0  = blockIdx.x * 128;
    const int bt0 = blockIdx.y * 64;
    const int tid = threadIdx.x;

    // folded reset: 8 blocks (y==0) zero g_h; block (0,0) zeroes counters+flags
    if (blockIdx.y == 0) {
        float* p = &g_h[0][0][0] + blockIdx.x * (2 * R_ * B_ / 8);
        for (int i = tid; i < 2 * R_ * B_ / 8; i += 256) p[i] = 0.0f;
        if (blockIdx.x == 0 && tid < NGRP * 32) {
            g_cnt[tid]  = 0u;
            g_flag[tid] = 0u;
        }
    }

    for (int idx = tid; idx < 64 * KTOT; idx += 256) {
        int row = idx / KTOT, col = idx - row * KTOT;
        float v = (col < F_) ? fb[(size_t)(bt0 + row) * F_ + col]
                             : drv[(size_t)(bt0 + row) * I_ + (col - F_)];
        xs[row][col] = v;
    }
    for (int idx = tid; idx < 128 * KTOT; idx += 256) {
        int row = idx / KTOT, col = idx - row * KTOT;
        int r = r0 + row;
        float v = (col < F_) ? Wfb[r * F_ + col] : Win[r * I_ + (col - F_)];
        wsh[row][col] = v;
    }
    __syncthreads();

    const int tx = tid & 15;
    const int ty = tid >> 4;

    float acc[4][8];
#pragma unroll
    for (int i = 0; i < 4; i++)
#pragma unroll
        for (int j = 0; j < 8; j++) acc[i][j] = 0.0f;

    for (int f = 0; f < KTOT; f++) {
        float x0 = xs[ty * 4 + 0][f];
        float x1 = xs[ty * 4 + 1][f];
        float x2 = xs[ty * 4 + 2][f];
        float x3 = xs[ty * 4 + 3][f];
        float w[8];
#pragma unroll
        for (int j = 0; j < 8; j++) w[j] = wsh[tx + 16 * j][f];
#pragma unroll
        for (int j = 0; j < 8; j++) {
            acc[0][j] = fmaf(x0, w[j], acc[0][j]);
            acc[1][j] = fmaf(x1, w[j], acc[1][j]);
            acc[2][j] = fmaf(x2, w[j], acc[2][j]);
            acc[3][j] = fmaf(x3, w[j], acc[3][j]);
        }
    }

#pragma unroll
    for (int j = 0; j < 8; j++) {
        int r = r0 + tx + 16 * j;
        float bv = bias[r];
#pragma unroll
        for (int i = 0; i < 4; i++) {
            size_t bt = (size_t)bt0 + ty * 4 + i;
            out[bt * R_ + r] = acc[i][j] + bv;
        }
    }
}

// ---------------- sequential scan: persistent, two-level grid barrier ----------------
__global__ __launch_bounds__(NTHR, 1) void scan_kernel(
    const float* __restrict__ Whh, float* __restrict__ out)
{
    __shared__ float2 partials[8][32];

    const int tid  = threadIdx.x;
    const int lane = tid & 31;
    const int warp = tid >> 5;
    const int r0   = blockIdx.x * 8;
    const int half = tid & 1;
    const int kq   = tid >> 1;
    const bool master = (blockIdx.x == 0);

    // preload W_hh slice, duplicated pairs {w,w}
    unsigned long long wd[8][8];
#pragma unroll
    for (int i = 0; i < 8; i++) {
        int k = kq + i * 128;
#pragma unroll
        for (int j = 0; j < 8; j++) {
            float w = Whh[(size_t)(r0 + j) * R_ + k];
            wd[i][j] = pack2(w, w);
        }
    }

    const float alpha = 0.9f;
    const float onem  = 1.0f - alpha;

    size_t oi0 = 0, oi1 = 0;
    float hprev0 = 0.0f, hprev1 = 0.0f;
    float pv0 = 0.0f, pv1 = 0.0f;        // deferred out-store values
    float nu0 = 0.0f, nu1 = 0.0f;        // prefetched drive values
    int er = 0, eb0 = 0, eb1 = 0;
    if (warp == 0) {
        int j = lane >> 2, p = lane & 3;
        er = r0 + j; eb0 = 2 * p; eb1 = eb0 + 1;
        oi0 = ((size_t)eb0 * T_) * R_ + er;
        oi1 = ((size_t)eb1 * T_) * R_ + er;
        nu0 = __ldcs(&out[oi0]);          // u(0)
        nu1 = __ldcs(&out[oi1]);
    }

    unsigned* my_cnt  = &g_cnt[(blockIdx.x & (NGRP - 1)) * 32];
    unsigned* my_flag = &g_flag[(blockIdx.x & (NGRP - 1)) * 32];

    for (int t = 0; t < T_; t++) {
        const int cur = t & 1, nxt = cur ^ 1;

        const float u0 = nu0, u1 = nu1;

        // deferred out stores for step t-1 (off every ordering path)
        if (warp == 0 && t > 0) {
            __stcg(&out[oi0 + (size_t)(t - 1) * R_], pv0);
            __stcg(&out[oi1 + (size_t)(t - 1) * R_], pv1);
        }

        // ---- load full h (L2, MLP=8) ----
        const float4* hsrc = reinterpret_cast<const float4*>(&g_h[cur][0][0]);
        float4 h4[8];
#pragma unroll
        for (int i = 0; i < 8; i++) {
            int k = kq + i * 128;
            h4[i] = __ldcg(hsrc + (k * 2 + half));
        }

        // ---- partial matvec: 8 k x 8 rows x 4 batches (f32x2) ----
        unsigned long long acc[16];
#pragma unroll
        for (int o = 0; o < 16; o++) acc[o] = 0ull;
#pragma unroll
        for (int i = 0; i < 8; i++) {
            unsigned long long h01 = pack2(h4[i].x, h4[i].y);
            unsigned long long h23 = pack2(h4[i].z, h4[i].w);
#pragma unroll
            for (int j = 0; j < 8; j++) {
                fma2(acc[j * 2 + 0], h01, wd[i][j]);
                fma2(acc[j * 2 + 1], h23, wd[i][j]);
            }
        }

        // ---- log-halving warp reduction ----
        reduce_round<8>(acc, lane, 2);
        reduce_round<4>(acc, lane, 4);
        reduce_round<2>(acc, lane, 8);
        reduce_round<1>(acc, lane, 16);

        {
            int o = (((lane >> 1) & 1) << 3) | (((lane >> 2) & 1) << 2) |
                    (((lane >> 3) & 1) << 1) | ((lane >> 4) & 1);
            int j = o >> 1, q = o & 1;
            int p = 2 * half + q;
            partials[warp][j * 4 + p] = unpack2(acc[0]);
        }
        __syncthreads();                                   // (A)

        // ---- epilogue: warp0, tree-add + tanh, h_prev in regs ----
        if (warp == 0) {
            float2 p0 = partials[0][lane], p1 = partials[1][lane];
            float2 p2 = partials[2][lane], p3 = partials[3][lane];
            float2 p4 = partials[4][lane], p5 = partials[5][lane];
            float2 p6 = partials[6][lane], p7 = partials[7][lane];
            float sx = ((p0.x + p1.x) + (p2.x + p3.x)) + ((p4.x + p5.x) + (p6.x + p7.x));
            float sy = ((p0.y + p1.y) + (p2.y + p3.y)) + ((p4.y + p5.y) + (p6.y + p7.y));

            float v0 = tanh_fast(onem * hprev0 + alpha * (u0 + sx));
            float v1 = tanh_fast(onem * hprev1 + alpha * (u1 + sy));
            __stcg(&g_h[nxt][er][eb0], v0);
            __stcg(&g_h[nxt][er][eb1], v1);
            hprev0 = v0; hprev1 = v1;
            pv0 = v0; pv1 = v1;
        }

        if (t < T_ - 1) {
            if (warp == 0) {
                // prefetch u(t+1): DRAM latency hidden under the barrier
                nu0 = __ldcs(&out[oi0 + (size_t)(t + 1) * R_]);
                nu1 = __ldcs(&out[oi1 + (size_t)(t + 1) * R_]);
                __syncwarp();                              // order g_h stores into lane 0
                if (lane == 0) {
                    // arrive (release covers warp0's g_h stores via syncwarp)
                    asm volatile("red.release.gpu.global.add.u32 [%0], %1;"
                                 :: "l"(my_cnt), "r"(1u) : "memory");
                    const unsigned epoch = (unsigned)(t + 1);
                    if (master) {
                        // level 1: master polls the 8 counters (relaxed, MLP=8)
                        const unsigned target = (unsigned)NBLK * epoch;
                        unsigned s;
                        do {
                            s = 0;
#pragma unroll
                            for (int g = 0; g < NGRP; g++) {
                                unsigned v;
                                asm volatile("ld.relaxed.gpu.u32 %0, [%1];"
                                             : "=r"(v) : "l"(&g_cnt[g * 32]) : "memory");
                                s += v;
                            }
                        } while (s < target);
                        asm volatile("fence.acq_rel.gpu;" ::: "memory");
                        // level 2: broadcast epoch on 8 clean flag lines
#pragma unroll
                        for (int g = 0; g < NGRP; g++) {
                            asm volatile("st.relaxed.gpu.global.u32 [%0], %1;"
                                         :: "l"(&g_flag[g * 32]), "r"(epoch) : "memory");
                        }
                    } else {
                        unsigned f;
                        do {
                            asm volatile("ld.relaxed.gpu.u32 %0, [%1];"
                                         : "=r"(f) : "l"(my_flag) : "memory");
                        } while (f < epoch);
                        asm volatile("fence.acq_rel.gpu;" ::: "memory");
                    }
                }
            }
            __syncthreads();                               // (C) release whole block
        }
    }

    // final out store for t = T-1
    if (warp == 0) {
        __stcg(&out[oi0 + (size_t)(T_ - 1) * R_], pv0);
        __stcg(&out[oi1 + (size_t)(T_ - 1) * R_], pv1);
    }
}

// ---------------- launch ----------------
extern "C" void kernel_launch(void* const* d_in, const int* in_sizes, int n_in,
                              void* d_out, int out_size)
{
    (void)in_sizes; (void)n_in; (void)out_size;
    const float* fb   = (const float*)d_in[0];
    const float* drv  = (const float*)d_in[1];
    const float* Wfb  = (const float*)d_in[2];
    const float* Win  = (const float*)d_in[3];
    const float* Whh  = (const float*)d_in[4];
    const float* bias = (const float*)d_in[5];
    float* out = (float*)d_out;

    cudaFuncSetAttribute(drive_kernel, cudaFuncAttributeMaxDynamicSharedMemorySize, DRIVE_SMEM);

    dim3 dgrid(R_ / 128, (B_ * T_) / 64);
    drive_kernel<<<dgrid, 256, DRIVE_SMEM>>>(fb, drv, Wfb, Win, bias, out);

    scan_kernel<<<NBLK, NTHR>>>(Whh, out);
}

// round 6
// speedup vs baseline: 1.8107x; 1.8107x over previous
#include <cuda_runtime.h>
#include <cstdint>

#define B_    8
#define T_    4096
#define R_    1024
#define F_    64
#define I_    32
#define KTOT  96            // F_ + I_
#define NBLK  128           // scan blocks (8 rows of W_hh each)
#define NTHR  256

// ---------------- device scratch (no allocations allowed) ----------------
__device__ float    g_h[2][R_][B_];                    // ping-pong hidden state [buf][k][b]
__device__ __align__(128) unsigned g_flag[NBLK * 32];  // 1 epoch flag per CTA, 1 per 128B line

// ---------------- helpers ----------------
__device__ __forceinline__ unsigned long long pack2(float a, float b) {
    unsigned long long r;
    asm("mov.b64 %0, {%1, %2};" : "=l"(r) : "f"(a), "f"(b));
    return r;
}
__device__ __forceinline__ void fma2(unsigned long long& d, unsigned long long a, unsigned long long b) {
    asm("fma.rn.f32x2 %0, %1, %2, %0;" : "+l"(d) : "l"(a), "l"(b));
}
__device__ __forceinline__ unsigned long long add2(unsigned long long a, unsigned long long b) {
    unsigned long long r;
    asm("add.rn.f32x2 %0, %1, %2;" : "=l"(r) : "l"(a), "l"(b));
    return r;
}
__device__ __forceinline__ float2 unpack2(unsigned long long v) {
    float2 f;
    asm("mov.b64 {%0, %1}, %2;" : "=f"(f.x), "=f"(f.y) : "l"(v));
    return f;
}
__device__ __forceinline__ float tanh_fast(float x) {
    float y;
    asm("tanh.approx.f32 %0, %1;" : "=f"(y) : "f"(x));
    return y;
}

template <int HALF>
__device__ __forceinline__ void reduce_round(unsigned long long* a, int lane, int d) {
    const bool hi = (lane & d) != 0;
#pragma unroll
    for (int i = 0; i < HALF; i++) {
        unsigned long long send = hi ? a[i] : a[i + HALF];
        unsigned long long keep = hi ? a[i + HALF] : a[i];
        unsigned long long recv = __shfl_xor_sync(0xffffffffu, send, d);
        a[i] = add2(keep, recv);
    }
}

// ---------------- drive GEMM (+ folded reset): out[bt][r] = X @ [Wfb|Win]^T + b ----
#define DRIVE_SMEM ((64 + 128) * 97 * 4)

__global__ __launch_bounds__(256) void drive_kernel(
    const float* __restrict__ fb, const float* __restrict__ drv,
    const float* __restrict__ Wfb, const float* __restrict__ Win,
    const float* __restrict__ bias, float* __restrict__ out)
{
    extern __shared__ float smem[];
    float (*xs)[97]  = (float (*)[97])smem;              // [64][97]
    float (*wsh)[97] = (float (*)[97])(smem + 64 * 97);  // [128][97]

    const int r0  = blockIdx.x * 128;
    const int bt0 = blockIdx.y * 64;
    const int tid = threadIdx.x;

    // folded reset: 8 blocks (y==0) zero g_h; block (0,0) zeroes the flags
    if (blockIdx.y == 0) {
        float* p = &g_h[0][0][0] + blockIdx.x * (2 * R_ * B_ / 8);
        for (int i = tid; i < 2 * R_ * B_ / 8; i += 256) p[i] = 0.0f;
        if (blockIdx.x == 0 && tid < NBLK) g_flag[tid * 32] = 0u;
    }

    for (int idx = tid; idx < 64 * KTOT; idx += 256) {
        int row = idx / KTOT, col = idx - row * KTOT;
        float v = (col < F_) ? fb[(size_t)(bt0 + row) * F_ + col]
                             : drv[(size_t)(bt0 + row) * I_ + (col - F_)];
        xs[row][col] = v;
    }
    for (int idx = tid; idx < 128 * KTOT; idx += 256) {
        int row = idx / KTOT, col = idx - row * KTOT;
        int r = r0 + row;
        float v = (col < F_) ? Wfb[r * F_ + col] : Win[r * I_ + (col - F_)];
        wsh[row][col] = v;
    }
    __syncthreads();

    const int tx = tid & 15;
    const int ty = tid >> 4;

    float acc[4][8];
#pragma unroll
    for (int i = 0; i < 4; i++)
#pragma unroll
        for (int j = 0; j < 8; j++) acc[i][j] = 0.0f;

    for (int f = 0; f < KTOT; f++) {
        float x0 = xs[ty * 4 + 0][f];
        float x1 = xs[ty * 4 + 1][f];
        float x2 = xs[ty * 4 + 2][f];
        float x3 = xs[ty * 4 + 3][f];
        float w[8];
#pragma unroll
        for (int j = 0; j < 8; j++) w[j] = wsh[tx + 16 * j][f];
#pragma unroll
        for (int j = 0; j < 8; j++) {
            acc[0][j] = fmaf(x0, w[j], acc[0][j]);
            acc[1][j] = fmaf(x1, w[j], acc[1][j]);
            acc[2][j] = fmaf(x2, w[j], acc[2][j]);
            acc[3][j] = fmaf(x3, w[j], acc[3][j]);
        }
    }

#pragma unroll
    for (int j = 0; j < 8; j++) {
        int r = r0 + tx + 16 * j;
        float bv = bias[r];
#pragma unroll
        for (int i = 0; i < 4; i++) {
            size_t bt = (size_t)bt0 + ty * 4 + i;
            out[bt * R_ + r] = acc[i][j] + bv;
        }
    }
}

// ---------------- sequential scan: persistent, flat flag barrier ----------------
__global__ __launch_bounds__(NTHR, 1) void scan_kernel(
    const float* __restrict__ Whh, float* __restrict__ out)
{
    __shared__ float2 partials[8][32];

    const int tid  = threadIdx.x;
    const int lane = tid & 31;
    const int warp = tid >> 5;
    const int r0   = blockIdx.x * 8;
    const int half = tid & 1;
    const int kq   = tid >> 1;

    // preload W_hh slice, duplicated pairs {w,w}
    unsigned long long wd[8][8];
#pragma unroll
    for (int i = 0; i < 8; i++) {
        int k = kq + i * 128;
#pragma unroll
        for (int j = 0; j < 8; j++) {
            float w = Whh[(size_t)(r0 + j) * R_ + k];
            wd[i][j] = pack2(w, w);
        }
    }

    const float alpha = 0.9f;
    const float onem  = 1.0f - alpha;

    size_t oi0 = 0, oi1 = 0;
    float hprev0 = 0.0f, hprev1 = 0.0f;
    float pv0 = 0.0f, pv1 = 0.0f;        // deferred out-store values
    int er = 0, eb0 = 0, eb1 = 0;
    if (warp == 0) {
        int j = lane >> 2, p = lane & 3;
        er = r0 + j; eb0 = 2 * p; eb1 = eb0 + 1;
        oi0 = ((size_t)eb0 * T_) * R_ + er;
        oi1 = ((size_t)eb1 * T_) * R_ + er;
    }

    unsigned* my_flag   = &g_flag[blockIdx.x * 32];
    unsigned* poll_flag = (tid < NBLK) ? &g_flag[tid * 32] : nullptr;

    for (int t = 0; t < T_; t++) {
        const int cur = t & 1, nxt = cur ^ 1;

        // ---- u(t) load + deferred out store: overlap with compute ----
        float u0 = 0.0f, u1 = 0.0f;
        if (warp == 0) {
            u0 = __ldcs(&out[oi0 + (size_t)t * R_]);
            u1 = __ldcs(&out[oi1 + (size_t)t * R_]);
            if (t > 0) {
                __stcg(&out[oi0 + (size_t)(t - 1) * R_], pv0);
                __stcg(&out[oi1 + (size_t)(t - 1) * R_], pv1);
            }
        }

        // ---- load full h (L2, MLP=8) ----
        const float4* hsrc = reinterpret_cast<const float4*>(&g_h[cur][0][0]);
        float4 h4[8];
#pragma unroll
        for (int i = 0; i < 8; i++) {
            int k = kq + i * 128;
            h4[i] = __ldcg(hsrc + (k * 2 + half));
        }

        // ---- partial matvec: 8 k x 8 rows x 4 batches (f32x2) ----
        unsigned long long acc[16];
#pragma unroll
        for (int o = 0; o < 16; o++) acc[o] = 0ull;
#pragma unroll
        for (int i = 0; i < 8; i++) {
            unsigned long long h01 = pack2(h4[i].x, h4[i].y);
            unsigned long long h23 = pack2(h4[i].z, h4[i].w);
#pragma unroll
            for (int j = 0; j < 8; j++) {
                fma2(acc[j * 2 + 0], h01, wd[i][j]);
                fma2(acc[j * 2 + 1], h23, wd[i][j]);
            }
        }

        // ---- log-halving warp reduction ----
        reduce_round<8>(acc, lane, 2);
        reduce_round<4>(acc, lane, 4);
        reduce_round<2>(acc, lane, 8);
        reduce_round<1>(acc, lane, 16);

        {
            int o = (((lane >> 1) & 1) << 3) | (((lane >> 2) & 1) << 2) |
                    (((lane >> 3) & 1) << 1) | ((lane >> 4) & 1);
            int j = o >> 1, q = o & 1;
            int p = 2 * half + q;
            partials[warp][j * 4 + p] = unpack2(acc[0]);
        }
        __syncthreads();                                   // (A)

        // ---- epilogue: warp0, tree-add + tanh, h_prev in regs ----
        if (warp == 0) {
            float2 p0 = partials[0][lane], p1 = partials[1][lane];
            float2 p2 = partials[2][lane], p3 = partials[3][lane];
            float2 p4 = partials[4][lane], p5 = partials[5][lane];
            float2 p6 = partials[6][lane], p7 = partials[7][lane];
            float sx = ((p0.x + p1.x) + (p2.x + p3.x)) + ((p4.x + p5.x) + (p6.x + p7.x));
            float sy = ((p0.y + p1.y) + (p2.y + p3.y)) + ((p4.y + p5.y) + (p6.y + p7.y));

            float v0 = tanh_fast(onem * hprev0 + alpha * (u0 + sx));
            float v1 = tanh_fast(onem * hprev1 + alpha * (u1 + sy));
            __stcg(&g_h[nxt][er][eb0], v0);
            __stcg(&g_h[nxt][er][eb1], v1);
            hprev0 = v0; hprev1 = v1;
            pv0 = v0; pv1 = v1;
        }

        if (t < T_ - 1) {
            const unsigned epoch = (unsigned)(t + 1);
            // ---- arrive: own flag line, plain release store (no atomics) ----
            if (warp == 0) {
                __syncwarp();   // order warp0's g_h stores before lane0's release
                if (lane == 0) {
                    asm volatile("st.release.gpu.global.u32 [%0], %1;"
                                 :: "l"(my_flag), "r"(epoch) : "memory");
                }
            }
            // ---- wait: thread i acquire-polls CTA i's flag; 128 checks in parallel ----
            if (tid < NBLK) {
                unsigned f;
                do {
                    asm volatile("ld.acquire.gpu.global.u32 %0, [%1];"
                                 : "=r"(f) : "l"(poll_flag) : "memory");
                } while (f < epoch);
            }
            __syncthreads();                               // (C) barrier complete
        }
    }

    // final out store for t = T-1
    if (warp == 0) {
        __stcg(&out[oi0 + (size_t)(T_ - 1) * R_], pv0);
        __stcg(&out[oi1 + (size_t)(T_ - 1) * R_], pv1);
    }
}

// ---------------- launch ----------------
extern "C" void kernel_launch(void* const* d_in, const int* in_sizes, int n_in,
                              void* d_out, int out_size)
{
    (void)in_sizes; (void)n_in; (void)out_size;
    const float* fb   = (const float*)d_in[0];
    const float* drv  = (const float*)d_in[1];
    const float* Wfb  = (const float*)d_in[2];
    const float* Win  = (const float*)d_in[3];
    const float* Whh  = (const float*)d_in[4];
    const float* bias = (const float*)d_in[5];
    float* out = (float*)d_out;

    cudaFuncSetAttribute(drive_kernel, cudaFuncAttributeMaxDynamicSharedMemorySize, DRIVE_SMEM);

    dim3 dgrid(R_ / 128, (B_ * T_) / 64);
    drive_kernel<<<dgrid, 256, DRIVE_SMEM>>>(fb, drv, Wfb, Win, bias, out);

    scan_kernel<<<NBLK, NTHR>>>(Whh, out);
}